// round 14
// baseline (speedup 1.0000x reference)
#include <cuda_runtime.h>
#include <math.h>
#include <stdint.h>

// Problem constants (B=4, H=W=32, Cin=256, Chid=1024)
#define DB   4
#define DN   1024          // H*W
#define DP   (DB*DN)       // 4096 rows (b,y,x)
#define CIN  256
#define CHID 1024
#define C2   512

// ---------------- scratch (static __device__ — allocation-guard safe) -------
__device__ __align__(256) float g_h  [DP*CHID];   // fc1 output, [p][c]
__device__ __align__(256) float g_y  [DP*CHID];   // concat / LN in-place
__device__ __align__(256) float g_d  [DP*C2];     // deform-conv output
__device__ __align__(256) float g_off[DP*64];     // offset-conv output
__device__ __align__(256) float g_col[DP*12800];  // im2col buffer (max K=25*512)
__device__ __align__(256) float g_wT [12800*512]; // transposed conv weights
__device__ __align__(256) float g_fT [CHID*CIN];  // transposed fc weights
__device__ __align__(256) float g_xr [DP*CIN];    // tf32-rounded x

// ---------------- tf32 rounding helper --------------------------------------
__device__ __forceinline__ float tf32r(float f) {
    uint32_t u;
    asm("cvt.rna.tf32.f32 %0, %1;" : "=r"(u) : "f"(f));
    return __uint_as_float(u);
}

// ---------------- producers (emit tf32-rounded GEMM inputs) ------------------
__global__ void round_copy(const float* __restrict__ src, float* __restrict__ dst,
                           int n) {
    int i = blockIdx.x * blockDim.x + threadIdx.x;
    if (i < n) dst[i] = tf32r(src[i]);
}

// Wt[k][n] = W[n][k]   (W is [Nout x K] row-major), tf32-rounded
__global__ void transpose_w(const float* __restrict__ W, float* __restrict__ Wt,
                            int Nout, int K) {
    int idx = blockIdx.x * blockDim.x + threadIdx.x;
    if (idx >= Nout * K) return;
    int n = idx % Nout, k = idx / Nout;
    Wt[(size_t)k * Nout + n] = tf32r(W[(size_t)n * K + k]);
}

// conv weight [O][C][k2] -> Wt[(j*C + c)][o], tf32-rounded
__global__ void transpose_convw(const float* __restrict__ W, float* __restrict__ Wt,
                                int O, int C, int k2) {
    int idx = blockIdx.x * blockDim.x + threadIdx.x;
    if (idx >= O * C * k2) return;
    int o = idx % O; int r = idx / O;
    int c = r % C;   int j = r / C;
    Wt[((size_t)j * C + c) * O + o] = tf32r(W[((size_t)o * C + c) * k2 + j]);
}

// ---------------- TF32 tensor-core GEMM (cp.async staged) -------------------
// C[M x Nn] = A[M x K] * B[K x Nn] + bias.  M%128==0, K%16==0.
// A, B must be pre-rounded to tf32 values. 128x128 block, 8 warps (2Mx4N),
// 64x32 warp tile via m16n8k8. A smem [m][k] stride 20, B smem [k][n] stride
// 136 — both conflict-free for fragment loads. Double buffered via cp.async.
// When Nn%4==0 the grid covers full tiles (callers guarantee) -> unguarded
// cp.async for B; otherwise scalar guarded STS fallback (skinny GEMMs).

__device__ __forceinline__ void mma_tf32(float c[4], uint32_t a0, uint32_t a1,
                                         uint32_t a2, uint32_t a3,
                                         uint32_t b0, uint32_t b1) {
    asm volatile(
        "mma.sync.aligned.m16n8k8.row.col.f32.tf32.tf32.f32 "
        "{%0,%1,%2,%3}, {%4,%5,%6,%7}, {%8,%9}, {%0,%1,%2,%3};\n"
        : "+f"(c[0]), "+f"(c[1]), "+f"(c[2]), "+f"(c[3])
        : "r"(a0), "r"(a1), "r"(a2), "r"(a3), "r"(b0), "r"(b1));
}

#define CP16(s, g) asm volatile("cp.async.cg.shared.global [%0], [%1], 16;\n" \
                                :: "r"(s), "l"(g))
#define CPCOMMIT() asm volatile("cp.async.commit_group;\n" ::: "memory")
#define CPWAIT0()  asm volatile("cp.async.wait_group 0;\n" ::: "memory")

#define ASTR 20    // A smem k-stride (16 + 4 pad): banks (ld4*20+lq)%32 bijective
#define BSTR 136   // B smem n-stride: banks (lq*8+ld4)%32 bijective

__global__ __launch_bounds__(256, 2)
void gemm_tc(const float* __restrict__ A, int lda,
             const float* __restrict__ B, const float* __restrict__ bias,
             float* __restrict__ C, int ldc, int ccol0,
             int M, int Nn, int K) {
    __shared__ float As[2][128][ASTR];
    __shared__ float Bs[2][16][BSTR];

    int tid  = threadIdx.x;
    int lane = tid & 31;
    int wid  = tid >> 5;
    int mW = (wid & 1) << 6;      // 0 / 64
    int nW = (wid >> 1) << 5;     // 0 / 32 / 64 / 96
    int lq  = lane & 3;
    int ld4 = lane >> 2;

    int blockRow = blockIdx.y << 7;
    int nB       = blockIdx.x << 7;
    const bool vec4 = ((Nn & 3) == 0);

    // staging maps
    int aRow = tid >> 1;                // 0..127
    int aK   = (tid & 1) << 2;          // 0 / 4   (plus +8 for second copy)
    int bRow = tid >> 4;                // 0..15
    int bCol = (tid & 15) << 2;         // 0..60   (plus +64 for second copy)

    const float* Apg = A + (size_t)(blockRow + aRow) * lda + aK;
    uint32_t sA0[2], sA1[2], sB0[2], sB1[2];
    #pragma unroll
    for (int bf = 0; bf < 2; bf++) {
        sA0[bf] = (uint32_t)__cvta_generic_to_shared(&As[bf][aRow][aK]);
        sA1[bf] = (uint32_t)__cvta_generic_to_shared(&As[bf][aRow][aK + 8]);
        sB0[bf] = (uint32_t)__cvta_generic_to_shared(&Bs[bf][bRow][bCol]);
        sB1[bf] = (uint32_t)__cvta_generic_to_shared(&Bs[bf][bRow][bCol + 64]);
    }

    float acc[4][4][4];
    #pragma unroll
    for (int i = 0; i < 4; i++)
        #pragma unroll
        for (int j = 0; j < 4; j++)
            #pragma unroll
            for (int q = 0; q < 4; q++) acc[i][j][q] = 0.f;

    int ntiles = K >> 4;

    // ---- stage tile 0 -> buffer 0 ----
    {
        CP16(sA0[0], Apg);
        CP16(sA1[0], Apg + 8);
        if (vec4) {
            const float* Bp = B + (size_t)bRow * Nn + nB + bCol;
            CP16(sB0[0], Bp);
            CP16(sB1[0], Bp + 64);
        } else {
            const float* Bp = B + (size_t)bRow * Nn;
            #pragma unroll
            for (int hh = 0; hh < 2; hh++) {
                int n0 = bCol + (hh << 6);
                #pragma unroll
                for (int e = 0; e < 4; e++)
                    Bs[0][bRow][n0 + e] = (n0 + e < Nn) ? Bp[n0 + e] : 0.f;
            }
        }
        CPCOMMIT();
    }
    CPWAIT0();
    __syncthreads();

    for (int t = 0; t < ntiles; t++) {
        int buf = t & 1;
        bool more = (t + 1 < ntiles);

        // ---- stage tile t+1 -> other buffer (overlaps compute) ----
        if (more) {
            int nb = buf ^ 1;
            int k0 = (t + 1) << 4;
            CP16(sA0[nb], Apg + k0);
            CP16(sA1[nb], Apg + k0 + 8);
            if (vec4) {
                const float* Bp = B + (size_t)(k0 + bRow) * Nn + nB + bCol;
                CP16(sB0[nb], Bp);
                CP16(sB1[nb], Bp + 64);
            } else {
                const float* Bp = B + (size_t)(k0 + bRow) * Nn;
                #pragma unroll
                for (int hh = 0; hh < 2; hh++) {
                    int n0 = bCol + (hh << 6);
                    #pragma unroll
                    for (int e = 0; e < 4; e++)
                        Bs[nb][bRow][n0 + e] = (n0 + e < Nn) ? Bp[n0 + e] : 0.f;
                }
            }
            CPCOMMIT();
        }

        // ---- compute on buffer `buf` ----
        #pragma unroll
        for (int ks = 0; ks < 2; ks++) {
            int kb = ks << 3;
            uint32_t a[4][4], b[4][2];
            #pragma unroll
            for (int fm = 0; fm < 4; fm++) {
                int m0 = mW + (fm << 4) + ld4;
                a[fm][0] = __float_as_uint(As[buf][m0    ][kb + lq    ]);
                a[fm][1] = __float_as_uint(As[buf][m0 + 8][kb + lq    ]);
                a[fm][2] = __float_as_uint(As[buf][m0    ][kb + lq + 4]);
                a[fm][3] = __float_as_uint(As[buf][m0 + 8][kb + lq + 4]);
            }
            #pragma unroll
            for (int fn = 0; fn < 4; fn++) {
                int n0 = nW + (fn << 3) + ld4;
                b[fn][0] = __float_as_uint(Bs[buf][kb + lq    ][n0]);
                b[fn][1] = __float_as_uint(Bs[buf][kb + lq + 4][n0]);
            }
            #pragma unroll
            for (int fm = 0; fm < 4; fm++)
                #pragma unroll
                for (int fn = 0; fn < 4; fn++)
                    mma_tf32(acc[fm][fn], a[fm][0], a[fm][1], a[fm][2], a[fm][3],
                             b[fn][0], b[fn][1]);
        }

        if (more) CPWAIT0();
        __syncthreads();
    }

    // ---- epilogue: bias + guarded store ----
    #pragma unroll
    for (int fm = 0; fm < 4; fm++) {
        int r0 = blockRow + mW + (fm << 4) + ld4;
        #pragma unroll
        for (int fn = 0; fn < 4; fn++) {
            int c0 = nB + nW + (fn << 3) + (lq << 1);
            float* Cp0 = C + (size_t)r0 * ldc + ccol0;
            float* Cp1 = C + (size_t)(r0 + 8) * ldc + ccol0;
            if (c0 < Nn) {
                float bz = bias[c0];
                Cp0[c0] = acc[fm][fn][0] + bz;
                Cp1[c0] = acc[fm][fn][2] + bz;
            }
            if (c0 + 1 < Nn) {
                float bz = bias[c0 + 1];
                Cp0[c0 + 1] = acc[fm][fn][1] + bz;
                Cp1[c0 + 1] = acc[fm][fn][3] + bz;
            }
        }
    }
}

// ---------------- im2col (regular, zero pad) — tf32-rounded output ----------
__global__ void im2col_reg(const float* __restrict__ src, int ld,
                           float* __restrict__ col, int k, int pad, int k2) {
    int idx = blockIdx.x * blockDim.x + threadIdx.x;
    int total = DP * k2 * 128;
    if (idx >= total) return;
    int c4 = idx & 127;
    int j  = (idx >> 7) % k2;
    int p  = idx / (k2 << 7);
    int b = p >> 10, n = p & 1023;
    int y = n >> 5, x = n & 31;
    int yy = y + j / k - pad;
    int xx = x + j % k - pad;
    float4 v = make_float4(0.f, 0.f, 0.f, 0.f);
    if ((unsigned)yy < 32u && (unsigned)xx < 32u) {
        float4 t = *(const float4*)(src + (size_t)((b << 10) + (yy << 5) + xx) * ld + (c4 << 2));
        v.x = tf32r(t.x); v.y = tf32r(t.y); v.z = tf32r(t.z); v.w = tf32r(t.w);
    }
    int K = k2 * C2;
    *(float4*)(col + (size_t)p * K + j * C2 + (c4 << 2)) = v;
}

// ---------------- im2col (deformable, bilinear) — tf32-rounded output -------
__global__ void im2col_def(const float* __restrict__ src, int ld,
                           const float* __restrict__ off, int ldo,
                           float* __restrict__ col, int k, int pad, int k2) {
    int idx = blockIdx.x * blockDim.x + threadIdx.x;
    int total = DP * k2 * 128;
    if (idx >= total) return;
    int c4 = idx & 127;
    int j  = (idx >> 7) % k2;
    int p  = idx / (k2 << 7);
    int b = p >> 10, n = p & 1023;
    int y = n >> 5, x = n & 31;

    float dy = off[(size_t)p * ldo + 2 * j];
    float dx = off[(size_t)p * ldo + 2 * j + 1];
    float py = (float)(y - pad + j / k) + dy;
    float px = (float)(x - pad + j % k) + dx;
    float y0 = floorf(py), x0 = floorf(px);
    float fy = py - y0,    fx = px - x0;
    int iy = (int)y0,      ix = (int)x0;
    float w00 = (1.f - fy) * (1.f - fx);
    float w01 = (1.f - fy) * fx;
    float w10 = fy * (1.f - fx);
    float w11 = fy * fx;

    const float* base = src + ((size_t)(b << 10)) * ld + (c4 << 2);
    float4 v = make_float4(0.f, 0.f, 0.f, 0.f);
#define CORNER(yc, xc, wt)                                                     \
    if ((unsigned)(yc) < 32u && (unsigned)(xc) < 32u) {                        \
        float4 t = *(const float4*)(base + (size_t)(((yc) << 5) + (xc)) * ld); \
        v.x += (wt) * t.x; v.y += (wt) * t.y;                                  \
        v.z += (wt) * t.z; v.w += (wt) * t.w;                                  \
    }
    CORNER(iy,     ix,     w00)
    CORNER(iy,     ix + 1, w01)
    CORNER(iy + 1, ix,     w10)
    CORNER(iy + 1, ix + 1, w11)
#undef CORNER
    v.x = tf32r(v.x); v.y = tf32r(v.y); v.z = tf32r(v.z); v.w = tf32r(v.w);

    int K = k2 * C2;
    *(float4*)(col + (size_t)p * K + j * C2 + (c4 << 2)) = v;
}

// ---------------- LayerNorm + exact GELU (tf32-rounded for fc2) -------------
__global__ void ln_gelu(float* __restrict__ y,
                        const float* __restrict__ gam, const float* __restrict__ bet) {
    int p = blockIdx.x;
    float* row = y + (size_t)p * CHID;
    int t = threadIdx.x;
    float4 v = ((const float4*)row)[t];
    float s  = v.x + v.y + v.z + v.w;
    float s2 = v.x * v.x + v.y * v.y + v.z * v.z + v.w * v.w;
    #pragma unroll
    for (int o = 16; o; o >>= 1) {
        s  += __shfl_down_sync(0xFFFFFFFFu, s,  o);
        s2 += __shfl_down_sync(0xFFFFFFFFu, s2, o);
    }
    __shared__ float sh[2][8];
    int w = t >> 5, l = t & 31;
    if (l == 0) { sh[0][w] = s; sh[1][w] = s2; }
    __syncthreads();
    if (t == 0) {
        float a = 0.f, b2 = 0.f;
        #pragma unroll
        for (int i = 0; i < 8; i++) { a += sh[0][i]; b2 += sh[1][i]; }
        sh[0][0] = a; sh[1][0] = b2;
    }
    __syncthreads();
    float mu  = sh[0][0] * (1.f / 1024.f);
    float var = sh[1][0] * (1.f / 1024.f) - mu * mu;
    float inv = rsqrtf(var + 1e-5f);
    float4 gg = ((const float4*)gam)[t];
    float4 bb = ((const float4*)bet)[t];
#define GEL(vv, gi, bi) do {                                       \
        float tv = (vv - mu) * inv * (gi) + (bi);                  \
        vv = tf32r(0.5f * tv * (1.f + erff(tv * 0.70710678118654752f))); \
    } while (0)
    GEL(v.x, gg.x, bb.x); GEL(v.y, gg.y, bb.y);
    GEL(v.z, gg.z, bb.z); GEL(v.w, gg.w, bb.w);
#undef GEL
    ((float4*)row)[t] = v;
}

// ---------------- orchestration ---------------------------------------------
extern "C" void kernel_launch(void* const* d_in, const int* in_sizes, int n_in,
                              void* d_out, int out_size) {
    const float* x       = (const float*)d_in[0];
    const float* fc1_w   = (const float*)d_in[3];
    const float* fc1_b   = (const float*)d_in[4];
    const float* off3_w  = (const float*)d_in[5];
    const float* off3_b  = (const float*)d_in[6];
    const float* conv3_w = (const float*)d_in[7];
    const float* conv3_b = (const float*)d_in[8];
    const float* off5_w  = (const float*)d_in[9];
    const float* off5_b  = (const float*)d_in[10];
    const float* conv5_w = (const float*)d_in[11];
    const float* conv5_b = (const float*)d_in[12];
    const float* lng     = (const float*)d_in[13];
    const float* lnb     = (const float*)d_in[14];
    const float* fc2_w   = (const float*)d_in[15];
    const float* fc2_b   = (const float*)d_in[16];
    float* out = (float*)d_out;

    float *h, *y, *d, *off, *col, *wT, *fT, *xr;
    cudaGetSymbolAddress((void**)&h,   g_h);
    cudaGetSymbolAddress((void**)&y,   g_y);
    cudaGetSymbolAddress((void**)&d,   g_d);
    cudaGetSymbolAddress((void**)&off, g_off);
    cudaGetSymbolAddress((void**)&col, g_col);
    cudaGetSymbolAddress((void**)&wT,  g_wT);
    cudaGetSymbolAddress((void**)&fT,  g_fT);
    cudaGetSymbolAddress((void**)&xr,  g_xr);

    // ---- fc1: h[P x 1024] = round(x)[P x 256] @ round(fc1_w)^T + b ----
    round_copy<<<(DP * CIN + 255) / 256, 256>>>(x, xr, DP * CIN);
    transpose_w<<<(CHID * CIN + 255) / 256, 256>>>(fc1_w, fT, CHID, CIN);
    gemm_tc<<<dim3(CHID / 128, DP / 128), 256>>>(xr, CIN, fT, fc1_b,
                                                 h, CHID, 0, DP, CHID, CIN);

    // ---- branch 1: k=3, pad=1, channels h[:, 0:512] -> y[:, 0:512] ----
    {
        const int k = 3, pad = 1, k2 = 9, K = k2 * C2, O = 2 * k2;
        const float* src = h;
        int icb = (DP * k2 * 128 + 255) / 256;
        transpose_convw<<<(O * C2 * k2 + 255) / 256, 256>>>(off3_w, wT, O, C2, k2);
        im2col_reg<<<icb, 256>>>(src, CHID, col, k, pad, k2);
        gemm_tc<<<dim3(1, DP / 128), 256>>>(col, K, wT, off3_b, off, O, 0, DP, O, K);
        transpose_convw<<<(C2 * C2 * k2 + 255) / 256, 256>>>(conv3_w, wT, C2, C2, k2);
        im2col_def<<<icb, 256>>>(src, CHID, off, O, col, k, pad, k2);
        gemm_tc<<<dim3(C2 / 128, DP / 128), 256>>>(col, K, wT, conv3_b,
                                                   d, C2, 0, DP, C2, K);
        im2col_reg<<<icb, 256>>>(d, C2, col, k, pad, k2);
        gemm_tc<<<dim3(C2 / 128, DP / 128), 256>>>(col, K, wT, conv3_b,
                                                   y, CHID, 0, DP, C2, K);
    }

    // ---- branch 2: k=5, pad=2, channels h[:, 512:1024] -> y[:, 512:1024] ----
    {
        const int k = 5, pad = 2, k2 = 25, K = k2 * C2, O = 2 * k2;
        const float* src = h + C2;
        int icb = (DP * k2 * 128 + 255) / 256;
        transpose_convw<<<(O * C2 * k2 + 255) / 256, 256>>>(off5_w, wT, O, C2, k2);
        im2col_reg<<<icb, 256>>>(src, CHID, col, k, pad, k2);
        gemm_tc<<<dim3(1, DP / 128), 256>>>(col, K, wT, off5_b, off, O, 0, DP, O, K);
        transpose_convw<<<(C2 * C2 * k2 + 255) / 256, 256>>>(conv5_w, wT, C2, C2, k2);
        im2col_def<<<icb, 256>>>(src, CHID, off, O, col, k, pad, k2);
        gemm_tc<<<dim3(C2 / 128, DP / 128), 256>>>(col, K, wT, conv5_b,
                                                   d, C2, 0, DP, C2, K);
        im2col_reg<<<icb, 256>>>(d, C2, col, k, pad, k2);
        gemm_tc<<<dim3(C2 / 128, DP / 128), 256>>>(col, K, wT, conv5_b,
                                                   y, CHID, C2, DP, C2, K);
    }

    // ---- LayerNorm + GELU (in place, rounds output for fc2) ----
    ln_gelu<<<DP, 256>>>(y, lng, lnb);

    // ---- fc2: out[P x 256] = y[P x 1024] @ round(fc2_w)^T + b ----
    transpose_w<<<(CIN * CHID + 255) / 256, 256>>>(fc2_w, fT, CIN, CHID);
    gemm_tc<<<dim3(CIN / 128, DP / 128), 256>>>(y, CHID, fT, fc2_b,
                                                out, CIN, 0, DP, CIN, CHID);
    (void)in_sizes; (void)n_in; (void)out_size;
}

// round 15
// speedup vs baseline: 1.6093x; 1.6093x over previous
#include <cuda_runtime.h>
#include <math.h>
#include <stdint.h>

// Problem constants (B=4, H=W=32, Cin=256, Chid=1024)
#define DB   4
#define DN   1024          // H*W
#define DP   (DB*DN)       // 4096 rows (b,y,x)
#define CIN  256
#define CHID 1024
#define C2   512
#define PLDC 512           // partial-buffer row stride
#define PSLAB ((size_t)DP*PLDC)

// ---------------- scratch (static __device__ — allocation-guard safe) -------
__device__ __align__(256) float g_h  [DP*CHID];   // fc1 output, [p][c]
__device__ __align__(256) float g_y  [DP*CHID];   // concat / LN in-place
__device__ __align__(256) float g_d  [DP*C2];     // deform-conv output
__device__ __align__(256) float g_off[DP*64];     // offset-conv output
__device__ __align__(256) float g_col[DP*12800];  // im2col buffer (max K=25*512)
__device__ __align__(256) float g_wT [12800*512]; // transposed conv weights
__device__ __align__(256) float g_fT [CHID*CIN];  // transposed fc weights
__device__ __align__(256) float g_xr [DP*CIN];    // tf32-rounded x
__device__ __align__(256) float g_part[4*DP*PLDC];// split-K partial sums

// ---------------- tf32 rounding helper --------------------------------------
__device__ __forceinline__ float tf32r(float f) {
    uint32_t u;
    asm("cvt.rna.tf32.f32 %0, %1;" : "=r"(u) : "f"(f));
    return __uint_as_float(u);
}

// ---------------- producers (emit tf32-rounded GEMM inputs) ------------------
__global__ void round_copy(const float* __restrict__ src, float* __restrict__ dst,
                           int n) {
    int i = blockIdx.x * blockDim.x + threadIdx.x;
    if (i < n) dst[i] = tf32r(src[i]);
}

// Wt[k][n] = W[n][k]   (W is [Nout x K] row-major), tf32-rounded
__global__ void transpose_w(const float* __restrict__ W, float* __restrict__ Wt,
                            int Nout, int K) {
    int idx = blockIdx.x * blockDim.x + threadIdx.x;
    if (idx >= Nout * K) return;
    int n = idx % Nout, k = idx / Nout;
    Wt[(size_t)k * Nout + n] = tf32r(W[(size_t)n * K + k]);
}

// conv weight [O][C][k2] -> Wt[(j*C + c)][o], tf32-rounded
__global__ void transpose_convw(const float* __restrict__ W, float* __restrict__ Wt,
                                int O, int C, int k2) {
    int idx = blockIdx.x * blockDim.x + threadIdx.x;
    if (idx >= O * C * k2) return;
    int o = idx % O; int r = idx / O;
    int c = r % C;   int j = r / C;
    Wt[((size_t)j * C + c) * O + o] = tf32r(W[((size_t)o * C + c) * k2 + j]);
}

// ---------------- TF32 tensor-core GEMM (cp.async staged, split-K) ----------
// gridDim.z = S splits K into S contiguous ranges (K/S % 16 == 0).
// S==1: C[M x Nn] = A*B + bias directly.
// S>1 : each z writes raw partial to part + z*PSLAB (row stride PLDC);
//       combine_parts() then sums + bias.

__device__ __forceinline__ void mma_tf32(float c[4], uint32_t a0, uint32_t a1,
                                         uint32_t a2, uint32_t a3,
                                         uint32_t b0, uint32_t b1) {
    asm volatile(
        "mma.sync.aligned.m16n8k8.row.col.f32.tf32.tf32.f32 "
        "{%0,%1,%2,%3}, {%4,%5,%6,%7}, {%8,%9}, {%0,%1,%2,%3};\n"
        : "+f"(c[0]), "+f"(c[1]), "+f"(c[2]), "+f"(c[3])
        : "r"(a0), "r"(a1), "r"(a2), "r"(a3), "r"(b0), "r"(b1));
}

#define CP16(s, g) asm volatile("cp.async.cg.shared.global [%0], [%1], 16;\n" \
                                :: "r"(s), "l"(g))
#define CPCOMMIT() asm volatile("cp.async.commit_group;\n" ::: "memory")
#define CPWAIT0()  asm volatile("cp.async.wait_group 0;\n" ::: "memory")

#define ASTR 20    // A smem k-stride (16 + 4 pad): banks (ld4*20+lq)%32 bijective
#define BSTR 136   // B smem n-stride: banks (lq*8+ld4)%32 bijective

__global__ __launch_bounds__(256, 2)
void gemm_tc(const float* __restrict__ A, int lda,
             const float* __restrict__ B, const float* __restrict__ bias,
             float* __restrict__ C, int ldc, int ccol0,
             int M, int Nn, int K, float* __restrict__ part) {
    __shared__ float As[2][128][ASTR];
    __shared__ float Bs[2][16][BSTR];

    int tid  = threadIdx.x;
    int lane = tid & 31;
    int wid  = tid >> 5;
    int mW = (wid & 1) << 6;      // 0 / 64
    int nW = (wid >> 1) << 5;     // 0 / 32 / 64 / 96
    int lq  = lane & 3;
    int ld4 = lane >> 2;

    int blockRow = blockIdx.y << 7;
    int nB       = blockIdx.x << 7;
    const bool vec4 = ((Nn & 3) == 0);

    int S    = gridDim.z;
    int kz   = blockIdx.z;
    int Kper = K / S;

    // staging maps
    int aRow = tid >> 1;                // 0..127
    int aK   = (tid & 1) << 2;          // 0 / 4   (plus +8 for second copy)
    int bRow = tid >> 4;                // 0..15
    int bCol = (tid & 15) << 2;         // 0..60   (plus +64 for second copy)

    const float* Apg   = A + (size_t)(blockRow + aRow) * lda + aK + (size_t)kz * Kper;
    const float* Bbase = B + (size_t)kz * Kper * Nn;
    uint32_t sA0[2], sA1[2], sB0[2], sB1[2];
    #pragma unroll
    for (int bf = 0; bf < 2; bf++) {
        sA0[bf] = (uint32_t)__cvta_generic_to_shared(&As[bf][aRow][aK]);
        sA1[bf] = (uint32_t)__cvta_generic_to_shared(&As[bf][aRow][aK + 8]);
        sB0[bf] = (uint32_t)__cvta_generic_to_shared(&Bs[bf][bRow][bCol]);
        sB1[bf] = (uint32_t)__cvta_generic_to_shared(&Bs[bf][bRow][bCol + 64]);
    }

    float acc[4][4][4];
    #pragma unroll
    for (int i = 0; i < 4; i++)
        #pragma unroll
        for (int j = 0; j < 4; j++)
            #pragma unroll
            for (int q = 0; q < 4; q++) acc[i][j][q] = 0.f;

    int ntiles = Kper >> 4;

    // ---- stage tile 0 -> buffer 0 ----
    {
        CP16(sA0[0], Apg);
        CP16(sA1[0], Apg + 8);
        if (vec4) {
            const float* Bp = Bbase + (size_t)bRow * Nn + nB + bCol;
            CP16(sB0[0], Bp);
            CP16(sB1[0], Bp + 64);
        } else {
            const float* Bp = Bbase + (size_t)bRow * Nn;
            #pragma unroll
            for (int hh = 0; hh < 2; hh++) {
                int n0 = bCol + (hh << 6);
                #pragma unroll
                for (int e = 0; e < 4; e++)
                    Bs[0][bRow][n0 + e] = (n0 + e < Nn) ? Bp[n0 + e] : 0.f;
            }
        }
        CPCOMMIT();
    }
    CPWAIT0();
    __syncthreads();

    for (int t = 0; t < ntiles; t++) {
        int buf = t & 1;
        bool more = (t + 1 < ntiles);

        // ---- stage tile t+1 -> other buffer (overlaps compute) ----
        if (more) {
            int nb = buf ^ 1;
            int k0 = (t + 1) << 4;
            CP16(sA0[nb], Apg + k0);
            CP16(sA1[nb], Apg + k0 + 8);
            if (vec4) {
                const float* Bp = Bbase + (size_t)(k0 + bRow) * Nn + nB + bCol;
                CP16(sB0[nb], Bp);
                CP16(sB1[nb], Bp + 64);
            } else {
                const float* Bp = Bbase + (size_t)(k0 + bRow) * Nn;
                #pragma unroll
                for (int hh = 0; hh < 2; hh++) {
                    int n0 = bCol + (hh << 6);
                    #pragma unroll
                    for (int e = 0; e < 4; e++)
                        Bs[nb][bRow][n0 + e] = (n0 + e < Nn) ? Bp[n0 + e] : 0.f;
                }
            }
            CPCOMMIT();
        }

        // ---- compute on buffer `buf` ----
        #pragma unroll
        for (int ks = 0; ks < 2; ks++) {
            int kb = ks << 3;
            uint32_t a[4][4], b[4][2];
            #pragma unroll
            for (int fm = 0; fm < 4; fm++) {
                int m0 = mW + (fm << 4) + ld4;
                a[fm][0] = __float_as_uint(As[buf][m0    ][kb + lq    ]);
                a[fm][1] = __float_as_uint(As[buf][m0 + 8][kb + lq    ]);
                a[fm][2] = __float_as_uint(As[buf][m0    ][kb + lq + 4]);
                a[fm][3] = __float_as_uint(As[buf][m0 + 8][kb + lq + 4]);
            }
            #pragma unroll
            for (int fn = 0; fn < 4; fn++) {
                int n0 = nW + (fn << 3) + ld4;
                b[fn][0] = __float_as_uint(Bs[buf][kb + lq    ][n0]);
                b[fn][1] = __float_as_uint(Bs[buf][kb + lq + 4][n0]);
            }
            #pragma unroll
            for (int fm = 0; fm < 4; fm++)
                #pragma unroll
                for (int fn = 0; fn < 4; fn++)
                    mma_tf32(acc[fm][fn], a[fm][0], a[fm][1], a[fm][2], a[fm][3],
                             b[fn][0], b[fn][1]);
        }

        if (more) CPWAIT0();
        __syncthreads();
    }

    // ---- epilogue ----
    if (S == 1) {
        #pragma unroll
        for (int fm = 0; fm < 4; fm++) {
            int r0 = blockRow + mW + (fm << 4) + ld4;
            #pragma unroll
            for (int fn = 0; fn < 4; fn++) {
                int c0 = nB + nW + (fn << 3) + (lq << 1);
                float* Cp0 = C + (size_t)r0 * ldc + ccol0;
                float* Cp1 = C + (size_t)(r0 + 8) * ldc + ccol0;
                if (c0 < Nn) {
                    float bz = bias[c0];
                    Cp0[c0] = acc[fm][fn][0] + bz;
                    Cp1[c0] = acc[fm][fn][2] + bz;
                }
                if (c0 + 1 < Nn) {
                    float bz = bias[c0 + 1];
                    Cp0[c0 + 1] = acc[fm][fn][1] + bz;
                    Cp1[c0 + 1] = acc[fm][fn][3] + bz;
                }
            }
        }
    } else {
        float* P = part + (size_t)kz * PSLAB;
        #pragma unroll
        for (int fm = 0; fm < 4; fm++) {
            int r0 = blockRow + mW + (fm << 4) + ld4;
            #pragma unroll
            for (int fn = 0; fn < 4; fn++) {
                int c0 = nB + nW + (fn << 3) + (lq << 1);
                float* Pp0 = P + (size_t)r0 * PLDC;
                float* Pp1 = P + (size_t)(r0 + 8) * PLDC;
                if (c0 < Nn) {
                    Pp0[c0] = acc[fm][fn][0];
                    Pp1[c0] = acc[fm][fn][2];
                }
                if (c0 + 1 < Nn) {
                    Pp0[c0 + 1] = acc[fm][fn][1];
                    Pp1[c0 + 1] = acc[fm][fn][3];
                }
            }
        }
    }
}

// ---------------- combine split-K partials + bias ---------------------------
__global__ void combine_parts(const float* __restrict__ part, int S,
                              const float* __restrict__ bias,
                              float* __restrict__ C, int ldc, int ccol0,
                              int M, int Nn) {
    int idx = blockIdx.x * blockDim.x + threadIdx.x;
    if (idx >= M * Nn) return;
    int p = idx / Nn, n = idx - p * Nn;
    float s = bias[n];
    for (int z = 0; z < S; z++)
        s += part[(size_t)z * PSLAB + (size_t)p * PLDC + n];
    C[(size_t)p * ldc + ccol0 + n] = s;
}

// ---------------- im2col (regular, zero pad) — tf32-rounded output ----------
__global__ void im2col_reg(const float* __restrict__ src, int ld,
                           float* __restrict__ col, int k, int pad, int k2) {
    int idx = blockIdx.x * blockDim.x + threadIdx.x;
    int total = DP * k2 * 128;
    if (idx >= total) return;
    int c4 = idx & 127;
    int j  = (idx >> 7) % k2;
    int p  = idx / (k2 << 7);
    int b = p >> 10, n = p & 1023;
    int y = n >> 5, x = n & 31;
    int yy = y + j / k - pad;
    int xx = x + j % k - pad;
    float4 v = make_float4(0.f, 0.f, 0.f, 0.f);
    if ((unsigned)yy < 32u && (unsigned)xx < 32u) {
        float4 t = *(const float4*)(src + (size_t)((b << 10) + (yy << 5) + xx) * ld + (c4 << 2));
        v.x = tf32r(t.x); v.y = tf32r(t.y); v.z = tf32r(t.z); v.w = tf32r(t.w);
    }
    int K = k2 * C2;
    *(float4*)(col + (size_t)p * K + j * C2 + (c4 << 2)) = v;
}

// ---------------- im2col (deformable, bilinear) — tf32-rounded output -------
__global__ void im2col_def(const float* __restrict__ src, int ld,
                           const float* __restrict__ off, int ldo,
                           float* __restrict__ col, int k, int pad, int k2) {
    int idx = blockIdx.x * blockDim.x + threadIdx.x;
    int total = DP * k2 * 128;
    if (idx >= total) return;
    int c4 = idx & 127;
    int j  = (idx >> 7) % k2;
    int p  = idx / (k2 << 7);
    int b = p >> 10, n = p & 1023;
    int y = n >> 5, x = n & 31;

    float dy = off[(size_t)p * ldo + 2 * j];
    float dx = off[(size_t)p * ldo + 2 * j + 1];
    float py = (float)(y - pad + j / k) + dy;
    float px = (float)(x - pad + j % k) + dx;
    float y0 = floorf(py), x0 = floorf(px);
    float fy = py - y0,    fx = px - x0;
    int iy = (int)y0,      ix = (int)x0;
    float w00 = (1.f - fy) * (1.f - fx);
    float w01 = (1.f - fy) * fx;
    float w10 = fy * (1.f - fx);
    float w11 = fy * fx;

    const float* base = src + ((size_t)(b << 10)) * ld + (c4 << 2);
    float4 v = make_float4(0.f, 0.f, 0.f, 0.f);
#define CORNER(yc, xc, wt)                                                     \
    if ((unsigned)(yc) < 32u && (unsigned)(xc) < 32u) {                        \
        float4 t = *(const float4*)(base + (size_t)(((yc) << 5) + (xc)) * ld); \
        v.x += (wt) * t.x; v.y += (wt) * t.y;                                  \
        v.z += (wt) * t.z; v.w += (wt) * t.w;                                  \
    }
    CORNER(iy,     ix,     w00)
    CORNER(iy,     ix + 1, w01)
    CORNER(iy + 1, ix,     w10)
    CORNER(iy + 1, ix + 1, w11)
#undef CORNER
    v.x = tf32r(v.x); v.y = tf32r(v.y); v.z = tf32r(v.z); v.w = tf32r(v.w);

    int K = k2 * C2;
    *(float4*)(col + (size_t)p * K + j * C2 + (c4 << 2)) = v;
}

// ---------------- LayerNorm + exact GELU (tf32-rounded for fc2) -------------
__global__ void ln_gelu(float* __restrict__ y,
                        const float* __restrict__ gam, const float* __restrict__ bet) {
    int p = blockIdx.x;
    float* row = y + (size_t)p * CHID;
    int t = threadIdx.x;
    float4 v = ((const float4*)row)[t];
    float s  = v.x + v.y + v.z + v.w;
    float s2 = v.x * v.x + v.y * v.y + v.z * v.z + v.w * v.w;
    #pragma unroll
    for (int o = 16; o; o >>= 1) {
        s  += __shfl_down_sync(0xFFFFFFFFu, s,  o);
        s2 += __shfl_down_sync(0xFFFFFFFFu, s2, o);
    }
    __shared__ float sh[2][8];
    int w = t >> 5, l = t & 31;
    if (l == 0) { sh[0][w] = s; sh[1][w] = s2; }
    __syncthreads();
    if (t == 0) {
        float a = 0.f, b2 = 0.f;
        #pragma unroll
        for (int i = 0; i < 8; i++) { a += sh[0][i]; b2 += sh[1][i]; }
        sh[0][0] = a; sh[1][0] = b2;
    }
    __syncthreads();
    float mu  = sh[0][0] * (1.f / 1024.f);
    float var = sh[1][0] * (1.f / 1024.f) - mu * mu;
    float inv = rsqrtf(var + 1e-5f);
    float4 gg = ((const float4*)gam)[t];
    float4 bb = ((const float4*)bet)[t];
#define GEL(vv, gi, bi) do {                                       \
        float tv = (vv - mu) * inv * (gi) + (bi);                  \
        vv = tf32r(0.5f * tv * (1.f + erff(tv * 0.70710678118654752f))); \
    } while (0)
    GEL(v.x, gg.x, bb.x); GEL(v.y, gg.y, bb.y);
    GEL(v.z, gg.z, bb.z); GEL(v.w, gg.w, bb.w);
#undef GEL
    ((float4*)row)[t] = v;
}

// ---------------- orchestration ---------------------------------------------
extern "C" void kernel_launch(void* const* d_in, const int* in_sizes, int n_in,
                              void* d_out, int out_size) {
    const float* x       = (const float*)d_in[0];
    const float* fc1_w   = (const float*)d_in[3];
    const float* fc1_b   = (const float*)d_in[4];
    const float* off3_w  = (const float*)d_in[5];
    const float* off3_b  = (const float*)d_in[6];
    const float* conv3_w = (const float*)d_in[7];
    const float* conv3_b = (const float*)d_in[8];
    const float* off5_w  = (const float*)d_in[9];
    const float* off5_b  = (const float*)d_in[10];
    const float* conv5_w = (const float*)d_in[11];
    const float* conv5_b = (const float*)d_in[12];
    const float* lng     = (const float*)d_in[13];
    const float* lnb     = (const float*)d_in[14];
    const float* fc2_w   = (const float*)d_in[15];
    const float* fc2_b   = (const float*)d_in[16];
    float* out = (float*)d_out;

    float *h, *y, *d, *off, *col, *wT, *fT, *xr, *part;
    cudaGetSymbolAddress((void**)&h,    g_h);
    cudaGetSymbolAddress((void**)&y,    g_y);
    cudaGetSymbolAddress((void**)&d,    g_d);
    cudaGetSymbolAddress((void**)&off,  g_off);
    cudaGetSymbolAddress((void**)&col,  g_col);
    cudaGetSymbolAddress((void**)&wT,   g_wT);
    cudaGetSymbolAddress((void**)&fT,   g_fT);
    cudaGetSymbolAddress((void**)&xr,   g_xr);
    cudaGetSymbolAddress((void**)&part, g_part);

    // ---- fc1: h = round(x) @ round(fc1_w)^T + b  (grid 256, no split) ----
    round_copy<<<(DP * CIN + 255) / 256, 256>>>(x, xr, DP * CIN);
    transpose_w<<<(CHID * CIN + 255) / 256, 256>>>(fc1_w, fT, CHID, CIN);
    gemm_tc<<<dim3(CHID / 128, DP / 128, 1), 256>>>(xr, CIN, fT, fc1_b,
                                                    h, CHID, 0, DP, CHID, CIN, part);

    // ---- branch 1: k=3, pad=1, channels h[:, 0:512] -> y[:, 0:512] ----
    {
        const int k = 3, pad = 1, k2 = 9, K = k2 * C2, O = 2 * k2;
        const float* src = h;
        int icb = (DP * k2 * 128 + 255) / 256;
        transpose_convw<<<(O * C2 * k2 + 255) / 256, 256>>>(off3_w, wT, O, C2, k2);
        im2col_reg<<<icb, 256>>>(src, CHID, col, k, pad, k2);
        gemm_tc<<<dim3(1, DP / 128, 4), 256>>>(col, K, wT, off3_b,
                                               off, O, 0, DP, O, K, part);
        combine_parts<<<(DP * O + 255) / 256, 256>>>(part, 4, off3_b, off, O, 0, DP, O);

        transpose_convw<<<(C2 * C2 * k2 + 255) / 256, 256>>>(conv3_w, wT, C2, C2, k2);
        im2col_def<<<icb, 256>>>(src, CHID, off, O, col, k, pad, k2);
        gemm_tc<<<dim3(C2 / 128, DP / 128, 2), 256>>>(col, K, wT, conv3_b,
                                                      d, C2, 0, DP, C2, K, part);
        combine_parts<<<(DP * C2 + 255) / 256, 256>>>(part, 2, conv3_b, d, C2, 0, DP, C2);

        im2col_reg<<<icb, 256>>>(d, C2, col, k, pad, k2);
        gemm_tc<<<dim3(C2 / 128, DP / 128, 2), 256>>>(col, K, wT, conv3_b,
                                                      y, CHID, 0, DP, C2, K, part);
        combine_parts<<<(DP * C2 + 255) / 256, 256>>>(part, 2, conv3_b, y, CHID, 0, DP, C2);
    }

    // ---- branch 2: k=5, pad=2, channels h[:, 512:1024] -> y[:, 512:1024] ----
    {
        const int k = 5, pad = 2, k2 = 25, K = k2 * C2, O = 2 * k2;
        const float* src = h + C2;
        int icb = (DP * k2 * 128 + 255) / 256;
        transpose_convw<<<(O * C2 * k2 + 255) / 256, 256>>>(off5_w, wT, O, C2, k2);
        im2col_reg<<<icb, 256>>>(src, CHID, col, k, pad, k2);
        gemm_tc<<<dim3(1, DP / 128, 4), 256>>>(col, K, wT, off5_b,
                                               off, O, 0, DP, O, K, part);
        combine_parts<<<(DP * O + 255) / 256, 256>>>(part, 4, off5_b, off, O, 0, DP, O);

        transpose_convw<<<(C2 * C2 * k2 + 255) / 256, 256>>>(conv5_w, wT, C2, C2, k2);
        im2col_def<<<icb, 256>>>(src, CHID, off, O, col, k, pad, k2);
        gemm_tc<<<dim3(C2 / 128, DP / 128, 2), 256>>>(col, K, wT, conv5_b,
                                                      d, C2, 0, DP, C2, K, part);
        combine_parts<<<(DP * C2 + 255) / 256, 256>>>(part, 2, conv5_b, d, C2, 0, DP, C2);

        im2col_reg<<<icb, 256>>>(d, C2, col, k, pad, k2);
        gemm_tc<<<dim3(C2 / 128, DP / 128, 2), 256>>>(col, K, wT, conv5_b,
                                                      y, CHID, C2, DP, C2, K, part);
        combine_parts<<<(DP * C2 + 255) / 256, 256>>>(part, 2, conv5_b, y, CHID, C2, DP, C2);
    }

    // ---- LayerNorm + GELU (in place, rounds output for fc2) ----
    ln_gelu<<<DP, 256>>>(y, lng, lnb);

    // ---- fc2: out = y @ round(fc2_w)^T + b  (split 4 -> 256 blocks) ----
    transpose_w<<<(CIN * CHID + 255) / 256, 256>>>(fc2_w, fT, CIN, CHID);
    gemm_tc<<<dim3(CIN / 128, DP / 128, 4), 256>>>(y, CHID, fT, fc2_b,
                                                   out, CIN, 0, DP, CIN, CHID, part);
    combine_parts<<<(DP * CIN + 255) / 256, 256>>>(part, 4, fc2_b, out, CIN, 0, DP, CIN);
    (void)in_sizes; (void)n_in; (void)out_size;
}

// round 17
// speedup vs baseline: 1.6325x; 1.0144x over previous
#include <cuda_runtime.h>
#include <math.h>
#include <stdint.h>

// Problem constants (B=4, H=W=32, Cin=256, Chid=1024)
#define DB   4
#define DN   1024
#define DP   (DB*DN)       // 4096 rows
#define CIN  256
#define CHID 1024
#define C2   512
#define PLDC 512
#define PSLAB ((size_t)DP*PLDC)

// ---------------- scratch ----------------------------------------------------
__device__ __align__(256) float g_h  [DP*CHID];
__device__ __align__(256) float g_y  [DP*CHID];
__device__ __align__(256) float g_d  [DP*C2];
__device__ __align__(256) float g_off[DP*64];
__device__ __align__(256) float g_col[DP*12800];
__device__ __align__(256) float g_wT [12800*512];  // weights [K][N]
__device__ __align__(256) float g_fT [CHID*CIN];
__device__ __align__(256) float g_xr [DP*CIN];
__device__ __align__(256) float g_part[4*DP*PLDC];

// ---------------- tf32 rounding ----------------------------------------------
__device__ __forceinline__ float tf32r(float f) {
    uint32_t u;
    asm("cvt.rna.tf32.f32 %0, %1;" : "=r"(u) : "f"(f));
    return __uint_as_float(u);
}

// ---------------- producers --------------------------------------------------
__global__ void round_copy(const float* __restrict__ src, float* __restrict__ dst,
                           int n) {
    int i = blockIdx.x * blockDim.x + threadIdx.x;
    if (i < n) dst[i] = tf32r(src[i]);
}

// Wt[k][n] = W[n][k]   (W is [Nout x K] row-major), tf32-rounded
__global__ void transpose_w(const float* __restrict__ W, float* __restrict__ Wt,
                            int Nout, int K) {
    int idx = blockIdx.x * blockDim.x + threadIdx.x;
    if (idx >= Nout * K) return;
    int n = idx % Nout, k = idx / Nout;
    Wt[(size_t)k * Nout + n] = tf32r(W[(size_t)n * K + k]);
}

// conv weight [O][C][k2] -> Wt[(j*C + c)][o], tf32-rounded
__global__ void transpose_convw(const float* __restrict__ W, float* __restrict__ Wt,
                                int O, int C, int k2) {
    int idx = blockIdx.x * blockDim.x + threadIdx.x;
    if (idx >= O * C * k2) return;
    int o = idx % O; int r = idx / O;
    int c = r % C;   int j = r / C;
    Wt[((size_t)j * C + c) * O + o] = tf32r(W[((size_t)o * C + c) * k2 + j]);
}

// ---------------- TF32 tensor-core GEMM --------------------------------------
// C[M x Nn] = A[M x K] * B[K x Nn] (+bias / split-K partial).
// 128 threads, 4 warps (2M x 2N), warp tile 64x64 via m16n8k8.
// BK=32 double-buffered cp.async chunks. A smem [m][k] stride 36,
// B smem [k][n] stride 136 — both bank-conflict-free for fragment loads.
// gridDim.z = S splits K (K/S % 32 == 0). S>1 -> raw partials, combine adds bias.

__device__ __forceinline__ void mma_tf32(float c[4], uint32_t a0, uint32_t a1,
                                         uint32_t a2, uint32_t a3,
                                         uint32_t b0, uint32_t b1) {
    asm volatile(
        "mma.sync.aligned.m16n8k8.row.col.f32.tf32.tf32.f32 "
        "{%0,%1,%2,%3}, {%4,%5,%6,%7}, {%8,%9}, {%0,%1,%2,%3};\n"
        : "+f"(c[0]), "+f"(c[1]), "+f"(c[2]), "+f"(c[3])
        : "r"(a0), "r"(a1), "r"(a2), "r"(a3), "r"(b0), "r"(b1));
}

#define CP16(s, g) asm volatile("cp.async.cg.shared.global [%0], [%1], 16;\n" \
                                :: "r"(s), "l"(g))
#define CPCOMMIT() asm volatile("cp.async.commit_group;\n" ::: "memory")
#define CPWAIT0()  asm volatile("cp.async.wait_group 0;\n" ::: "memory")

#define ASTR 36    // A smem k-stride: banks ((l>>2)*36+(l&3))%32 = (l>>2)*4+(l&3) bijective
#define BSTR 136   // B smem n-stride: banks ((l&3)*136+(l>>2))%32 = (l&3)*8+(l>>2) bijective
#define ABYTES (128*ASTR*4)     // 18432 per buffer
#define BBYTES (32*BSTR*4)      // 17408 per buffer
#define GSMEM  (2*ABYTES + 2*BBYTES)   // 71680

__global__ __launch_bounds__(128, 2)
void gemm_tc(const float* __restrict__ A, int lda,
             const float* __restrict__ B, const float* __restrict__ bias,
             float* __restrict__ C, int ldc, int ccol0,
             int M, int Nn, int K, float* __restrict__ part) {
    extern __shared__ float sm[];
    float* Asm[2] = { sm, sm + 128 * ASTR };
    float* Bsm[2] = { sm + 2 * 128 * ASTR, sm + 2 * 128 * ASTR + 32 * BSTR };

    int tid  = threadIdx.x;
    int lane = tid & 31;
    int wid  = tid >> 5;
    int mW = (wid & 1) << 6;      // 0 / 64
    int nW = (wid >> 1) << 6;     // 0 / 64
    int lq  = lane & 3;
    int ld4 = lane >> 2;

    int blockRow = blockIdx.y << 7;
    int nB       = blockIdx.x << 7;
    const bool vec4 = ((Nn & 3) == 0);   // big GEMMs: full 128-wide tiles

    int S = gridDim.z, kz = blockIdx.z;
    int Kper = K / S;

    // staging maps
    // A: thread t stages row t (32 floats = 8x16B)
    const float* aSrc = A + (size_t)(blockRow + tid) * lda + (size_t)kz * Kper;
    // B: thread t stages row t>>2 (of 32), chunks (t&3)+4j, j=0..7
    int bR  = tid >> 2;
    int bC0 = (tid & 3) << 2;            // float offset of first chunk
    const float* bSrcRow = B + (size_t)kz * Kper * Nn;

    uint32_t sA[2], sB[2];
    #pragma unroll
    for (int bf = 0; bf < 2; bf++) {
        sA[bf] = (uint32_t)__cvta_generic_to_shared(Asm[bf] + tid * ASTR);
        sB[bf] = (uint32_t)__cvta_generic_to_shared(Bsm[bf] + bR * BSTR + bC0);
    }

    float acc[4][8][4];
    #pragma unroll
    for (int i = 0; i < 4; i++)
        #pragma unroll
        for (int j = 0; j < 8; j++)
            #pragma unroll
            for (int q = 0; q < 4; q++) acc[i][j][q] = 0.f;

    int nch = Kper >> 5;

    // ---- stage chunk 0 -> buffer 0 ----
    {
        #pragma unroll
        for (int i = 0; i < 8; i++) CP16(sA[0] + i * 16, aSrc + i * 4);
        if (vec4) {
            const float* Bp = bSrcRow + (size_t)bR * Nn + nB + bC0;
            #pragma unroll
            for (int j = 0; j < 8; j++) CP16(sB[0] + j * 64, Bp + j * 16);
        } else {
            const float* Bp = bSrcRow + (size_t)bR * Nn;
            #pragma unroll
            for (int j = 0; j < 8; j++) {
                float4 v;
                int n0 = nB + bC0 + j * 16;
                v.x = (n0 + 0 < Nn) ? Bp[n0 + 0] : 0.f;
                v.y = (n0 + 1 < Nn) ? Bp[n0 + 1] : 0.f;
                v.z = (n0 + 2 < Nn) ? Bp[n0 + 2] : 0.f;
                v.w = (n0 + 3 < Nn) ? Bp[n0 + 3] : 0.f;
                *(float4*)(Bsm[0] + bR * BSTR + bC0 + j * 16) = v;
            }
        }
        CPCOMMIT();
    }
    CPWAIT0();
    __syncthreads();

    for (int t = 0; t < nch; t++) {
        int buf = t & 1;
        bool more = (t + 1 < nch);

        // ---- stage chunk t+1 (overlaps compute) ----
        if (more) {
            int nb = buf ^ 1;
            int k0 = (t + 1) << 5;
            #pragma unroll
            for (int i = 0; i < 8; i++) CP16(sA[nb] + i * 16, aSrc + k0 + i * 4);
            if (vec4) {
                const float* Bp = bSrcRow + (size_t)(k0 + bR) * Nn + nB + bC0;
                #pragma unroll
                for (int j = 0; j < 8; j++) CP16(sB[nb] + j * 64, Bp + j * 16);
            } else {
                const float* Bp = bSrcRow + (size_t)(k0 + bR) * Nn;
                #pragma unroll
                for (int j = 0; j < 8; j++) {
                    float4 v;
                    int n0 = nB + bC0 + j * 16;
                    v.x = (n0 + 0 < Nn) ? Bp[n0 + 0] : 0.f;
                    v.y = (n0 + 1 < Nn) ? Bp[n0 + 1] : 0.f;
                    v.z = (n0 + 2 < Nn) ? Bp[n0 + 2] : 0.f;
                    v.w = (n0 + 3 < Nn) ? Bp[n0 + 3] : 0.f;
                    *(float4*)(Bsm[nb] + bR * BSTR + bC0 + j * 16) = v;
                }
            }
            CPCOMMIT();
        }

        // ---- compute: 4 k8-steps on buffer `buf` ----
        const float* Ab = Asm[buf];
        const float* Bb = Bsm[buf];
        #pragma unroll
        for (int ks = 0; ks < 4; ks++) {
            int kb = ks << 3;
            uint32_t a[4][4], b[8][2];
            #pragma unroll
            for (int fm = 0; fm < 4; fm++) {
                int m0 = mW + (fm << 4) + ld4;
                a[fm][0] = __float_as_uint(Ab[(m0    ) * ASTR + kb + lq    ]);
                a[fm][1] = __float_as_uint(Ab[(m0 + 8) * ASTR + kb + lq    ]);
                a[fm][2] = __float_as_uint(Ab[(m0    ) * ASTR + kb + lq + 4]);
                a[fm][3] = __float_as_uint(Ab[(m0 + 8) * ASTR + kb + lq + 4]);
            }
            #pragma unroll
            for (int fn = 0; fn < 8; fn++) {
                int n0 = nW + (fn << 3) + ld4;
                b[fn][0] = __float_as_uint(Bb[(kb + lq    ) * BSTR + n0]);
                b[fn][1] = __float_as_uint(Bb[(kb + lq + 4) * BSTR + n0]);
            }
            #pragma unroll
            for (int fm = 0; fm < 4; fm++)
                #pragma unroll
                for (int fn = 0; fn < 8; fn++)
                    mma_tf32(acc[fm][fn], a[fm][0], a[fm][1], a[fm][2], a[fm][3],
                             b[fn][0], b[fn][1]);
        }

        if (more) CPWAIT0();
        __syncthreads();
    }

    // ---- epilogue ----
    #pragma unroll
    for (int fm = 0; fm < 4; fm++) {
        int r0 = blockRow + mW + (fm << 4) + ld4;
        if (S == 1) {
            float* Cp0 = C + (size_t)r0 * ldc + ccol0;
            float* Cp1 = C + (size_t)(r0 + 8) * ldc + ccol0;
            #pragma unroll
            for (int fn = 0; fn < 8; fn++) {
                int c0 = nB + nW + (fn << 3) + (lq << 1);
                if (c0 < Nn) {
                    float bz = bias[c0];
                    Cp0[c0] = acc[fm][fn][0] + bz;
                    Cp1[c0] = acc[fm][fn][2] + bz;
                }
                if (c0 + 1 < Nn) {
                    float bz = bias[c0 + 1];
                    Cp0[c0 + 1] = acc[fm][fn][1] + bz;
                    Cp1[c0 + 1] = acc[fm][fn][3] + bz;
                }
            }
        } else {
            float* Pp0 = part + (size_t)kz * PSLAB + (size_t)r0 * PLDC;
            float* Pp1 = Pp0 + 8 * PLDC;
            #pragma unroll
            for (int fn = 0; fn < 8; fn++) {
                int c0 = nB + nW + (fn << 3) + (lq << 1);
                if (c0 < Nn) {
                    Pp0[c0] = acc[fm][fn][0];
                    Pp1[c0] = acc[fm][fn][2];
                }
                if (c0 + 1 < Nn) {
                    Pp0[c0 + 1] = acc[fm][fn][1];
                    Pp1[c0 + 1] = acc[fm][fn][3];
                }
            }
        }
    }
}

// ---------------- combine split-K partials + bias ----------------------------
__global__ void combine_parts(const float* __restrict__ part, int S,
                              const float* __restrict__ bias,
                              float* __restrict__ C, int ldc, int ccol0,
                              int M, int Nn) {
    int idx = blockIdx.x * blockDim.x + threadIdx.x;
    if (idx >= M * Nn) return;
    int p = idx / Nn, n = idx - p * Nn;
    float s = bias[n];
    for (int z = 0; z < S; z++)
        s += part[(size_t)z * PSLAB + (size_t)p * PLDC + n];
    C[(size_t)p * ldc + ccol0 + n] = s;
}

// ---------------- im2col (regular) — tf32-rounded ----------------------------
__global__ void im2col_reg(const float* __restrict__ src, int ld,
                           float* __restrict__ col, int k, int pad, int k2) {
    int idx = blockIdx.x * blockDim.x + threadIdx.x;
    int total = DP * k2 * 128;
    if (idx >= total) return;
    int c4 = idx & 127;
    int j  = (idx >> 7) % k2;
    int p  = idx / (k2 << 7);
    int b = p >> 10, n = p & 1023;
    int y = n >> 5, x = n & 31;
    int yy = y + j / k - pad;
    int xx = x + j % k - pad;
    float4 v = make_float4(0.f, 0.f, 0.f, 0.f);
    if ((unsigned)yy < 32u && (unsigned)xx < 32u) {
        float4 t = *(const float4*)(src + (size_t)((b << 10) + (yy << 5) + xx) * ld + (c4 << 2));
        v.x = tf32r(t.x); v.y = tf32r(t.y); v.z = tf32r(t.z); v.w = tf32r(t.w);
    }
    int K = k2 * C2;
    *(float4*)(col + (size_t)p * K + j * C2 + (c4 << 2)) = v;
}

// ---------------- im2col (deformable, bilinear) — tf32-rounded ---------------
__global__ void im2col_def(const float* __restrict__ src, int ld,
                           const float* __restrict__ off, int ldo,
                           float* __restrict__ col, int k, int pad, int k2) {
    int idx = blockIdx.x * blockDim.x + threadIdx.x;
    int total = DP * k2 * 128;
    if (idx >= total) return;
    int c4 = idx & 127;
    int j  = (idx >> 7) % k2;
    int p  = idx / (k2 << 7);
    int b = p >> 10, n = p & 1023;
    int y = n >> 5, x = n & 31;

    float dy = off[(size_t)p * ldo + 2 * j];
    float dx = off[(size_t)p * ldo + 2 * j + 1];
    float py = (float)(y - pad + j / k) + dy;
    float px = (float)(x - pad + j % k) + dx;
    float y0 = floorf(py), x0 = floorf(px);
    float fy = py - y0,    fx = px - x0;
    int iy = (int)y0,      ix = (int)x0;
    float w00 = (1.f - fy) * (1.f - fx);
    float w01 = (1.f - fy) * fx;
    float w10 = fy * (1.f - fx);
    float w11 = fy * fx;

    const float* base = src + ((size_t)(b << 10)) * ld + (c4 << 2);
    float4 v = make_float4(0.f, 0.f, 0.f, 0.f);
#define CORNER(yc, xc, wt)                                                     \
    if ((unsigned)(yc) < 32u && (unsigned)(xc) < 32u) {                        \
        float4 t = *(const float4*)(base + (size_t)(((yc) << 5) + (xc)) * ld); \
        v.x += (wt) * t.x; v.y += (wt) * t.y;                                  \
        v.z += (wt) * t.z; v.w += (wt) * t.w;                                  \
    }
    CORNER(iy,     ix,     w00)
    CORNER(iy,     ix + 1, w01)
    CORNER(iy + 1, ix,     w10)
    CORNER(iy + 1, ix + 1, w11)
#undef CORNER
    v.x = tf32r(v.x); v.y = tf32r(v.y); v.z = tf32r(v.z); v.w = tf32r(v.w);

    int K = k2 * C2;
    *(float4*)(col + (size_t)p * K + j * C2 + (c4 << 2)) = v;
}

// ---------------- LayerNorm + exact GELU -------------------------------------
__global__ void ln_gelu(float* __restrict__ y,
                        const float* __restrict__ gam, const float* __restrict__ bet) {
    int p = blockIdx.x;
    float* row = y + (size_t)p * CHID;
    int t = threadIdx.x;
    float4 v = ((const float4*)row)[t];
    float s  = v.x + v.y + v.z + v.w;
    float s2 = v.x * v.x + v.y * v.y + v.z * v.z + v.w * v.w;
    #pragma unroll
    for (int o = 16; o; o >>= 1) {
        s  += __shfl_down_sync(0xFFFFFFFFu, s,  o);
        s2 += __shfl_down_sync(0xFFFFFFFFu, s2, o);
    }
    __shared__ float sh[2][8];
    int w = t >> 5, l = t & 31;
    if (l == 0) { sh[0][w] = s; sh[1][w] = s2; }
    __syncthreads();
    if (t == 0) {
        float a = 0.f, b2 = 0.f;
        #pragma unroll
        for (int i = 0; i < 8; i++) { a += sh[0][i]; b2 += sh[1][i]; }
        sh[0][0] = a; sh[1][0] = b2;
    }
    __syncthreads();
    float mu  = sh[0][0] * (1.f / 1024.f);
    float var = sh[1][0] * (1.f / 1024.f) - mu * mu;
    float inv = rsqrtf(var + 1e-5f);
    float4 gg = ((const float4*)gam)[t];
    float4 bb = ((const float4*)bet)[t];
#define GEL(vv, gi, bi) do {                                       \
        float tv = (vv - mu) * inv * (gi) + (bi);                  \
        vv = tf32r(0.5f * tv * (1.f + erff(tv * 0.70710678118654752f))); \
    } while (0)
    GEL(v.x, gg.x, bb.x); GEL(v.y, gg.y, bb.y);
    GEL(v.z, gg.z, bb.z); GEL(v.w, gg.w, bb.w);
#undef GEL
    ((float4*)row)[t] = v;
}

// ---------------- orchestration ----------------------------------------------
extern "C" void kernel_launch(void* const* d_in, const int* in_sizes, int n_in,
                              void* d_out, int out_size) {
    const float* x       = (const float*)d_in[0];
    const float* fc1_w   = (const float*)d_in[3];
    const float* fc1_b   = (const float*)d_in[4];
    const float* off3_w  = (const float*)d_in[5];
    const float* off3_b  = (const float*)d_in[6];
    const float* conv3_w = (const float*)d_in[7];
    const float* conv3_b = (const float*)d_in[8];
    const float* off5_w  = (const float*)d_in[9];
    const float* off5_b  = (const float*)d_in[10];
    const float* conv5_w = (const float*)d_in[11];
    const float* conv5_b = (const float*)d_in[12];
    const float* lng     = (const float*)d_in[13];
    const float* lnb     = (const float*)d_in[14];
    const float* fc2_w   = (const float*)d_in[15];
    const float* fc2_b   = (const float*)d_in[16];
    float* out = (float*)d_out;

    float *h, *y, *d, *off, *col, *wT, *fT, *xr, *part;
    cudaGetSymbolAddress((void**)&h,    g_h);
    cudaGetSymbolAddress((void**)&y,    g_y);
    cudaGetSymbolAddress((void**)&d,    g_d);
    cudaGetSymbolAddress((void**)&off,  g_off);
    cudaGetSymbolAddress((void**)&col,  g_col);
    cudaGetSymbolAddress((void**)&wT,   g_wT);
    cudaGetSymbolAddress((void**)&fT,   g_fT);
    cudaGetSymbolAddress((void**)&xr,   g_xr);
    cudaGetSymbolAddress((void**)&part, g_part);

    cudaFuncSetAttribute(gemm_tc, cudaFuncAttributeMaxDynamicSharedMemorySize, GSMEM);

    // ---- fc1: h = round(x) @ round(fc1_w)^T + b  (grid 256) ----
    round_copy<<<(DP * CIN + 255) / 256, 256>>>(x, xr, DP * CIN);
    transpose_w<<<(CHID * CIN + 255) / 256, 256>>>(fc1_w, fT, CHID, CIN);
    gemm_tc<<<dim3(CHID / 128, DP / 128, 1), 128, GSMEM>>>(
        xr, CIN, fT, fc1_b, h, CHID, 0, DP, CHID, CIN, part);

    // ---- branch 1: k=3, pad=1, h[:, 0:512] -> y[:, 0:512] ----
    {
        const int k = 3, pad = 1, k2 = 9, K = k2 * C2, O = 2 * k2;
        const float* src = h;
        int icb = (DP * k2 * 128 + 255) / 256;
        transpose_convw<<<(O * C2 * k2 + 255) / 256, 256>>>(off3_w, wT, O, C2, k2);
        im2col_reg<<<icb, 256>>>(src, CHID, col, k, pad, k2);
        gemm_tc<<<dim3(1, DP / 128, 4), 128, GSMEM>>>(
            col, K, wT, off3_b, off, O, 0, DP, O, K, part);
        combine_parts<<<(DP * O + 255) / 256, 256>>>(part, 4, off3_b, off, O, 0, DP, O);

        transpose_convw<<<(C2 * C2 * k2 + 255) / 256, 256>>>(conv3_w, wT, C2, C2, k2);
        im2col_def<<<icb, 256>>>(src, CHID, off, O, col, k, pad, k2);
        gemm_tc<<<dim3(C2 / 128, DP / 128, 2), 128, GSMEM>>>(
            col, K, wT, conv3_b, d, C2, 0, DP, C2, K, part);
        combine_parts<<<(DP * C2 + 255) / 256, 256>>>(part, 2, conv3_b, d, C2, 0, DP, C2);

        im2col_reg<<<icb, 256>>>(d, C2, col, k, pad, k2);
        gemm_tc<<<dim3(C2 / 128, DP / 128, 2), 128, GSMEM>>>(
            col, K, wT, conv3_b, y, CHID, 0, DP, C2, K, part);
        combine_parts<<<(DP * C2 + 255) / 256, 256>>>(part, 2, conv3_b, y, CHID, 0, DP, C2);
    }

    // ---- branch 2: k=5, pad=2, h[:, 512:1024] -> y[:, 512:1024] ----
    {
        const int k = 5, pad = 2, k2 = 25, K = k2 * C2, O = 2 * k2;
        const float* src = h + C2;
        int icb = (DP * k2 * 128 + 255) / 256;
        transpose_convw<<<(O * C2 * k2 + 255) / 256, 256>>>(off5_w, wT, O, C2, k2);
        im2col_reg<<<icb, 256>>>(src, CHID, col, k, pad, k2);
        gemm_tc<<<dim3(1, DP / 128, 4), 128, GSMEM>>>(
            col, K, wT, off5_b, off, O, 0, DP, O, K, part);
        combine_parts<<<(DP * O + 255) / 256, 256>>>(part, 4, off5_b, off, O, 0, DP, O);

        transpose_convw<<<(C2 * C2 * k2 + 255) / 256, 256>>>(conv5_w, wT, C2, C2, k2);
        im2col_def<<<icb, 256>>>(src, CHID, off, O, col, k, pad, k2);
        gemm_tc<<<dim3(C2 / 128, DP / 128, 2), 128, GSMEM>>>(
            col, K, wT, conv5_b, d, C2, 0, DP, C2, K, part);
        combine_parts<<<(DP * C2 + 255) / 256, 256>>>(part, 2, conv5_b, d, C2, 0, DP, C2);

        im2col_reg<<<icb, 256>>>(d, C2, col, k, pad, k2);
        gemm_tc<<<dim3(C2 / 128, DP / 128, 2), 128, GSMEM>>>(
            col, K, wT, conv5_b, y, CHID, C2, DP, C2, K, part);
        combine_parts<<<(DP * C2 + 255) / 256, 256>>>(part, 2, conv5_b, y, CHID, C2, DP, C2);
    }

    // ---- LayerNorm + GELU ----
    ln_gelu<<<DP, 256>>>(y, lng, lnb);

    // ---- fc2: out = y @ round(fc2_w)^T + b  (split 4 -> 256 blocks) ----
    transpose_w<<<(CIN * CHID + 255) / 256, 256>>>(fc2_w, fT, CIN, CHID);
    gemm_tc<<<dim3(CIN / 128, DP / 128, 4), 128, GSMEM>>>(
        y, CHID, fT, fc2_b, out, CIN, 0, DP, CIN, CHID, part);
    combine_parts<<<(DP * CIN + 255) / 256, 256>>>(part, 4, fc2_b, out, CIN, 0, DP, CIN);
    (void)in_sizes; (void)n_in; (void)out_size;
}